// round 10
// baseline (speedup 1.0000x reference)
#include <cuda_runtime.h>

// crossMSEloss: B=4, S=256, P=64, D=63
// out[b,s] = sum_p conf[p] * min_q ||pred_p - tgt_q||
//          + sum_q min_p ( ||pred_p - tgt_q|| / conf[p] )
//
// Persistent blocks (304 = 2/SM), each handling ~3-4 (b,s) tiles with a
// cp.async double-buffered gmem->smem staging pipeline: tile t+1 streams from
// DRAM while tile t computes (the kernel was memory-duty-cycle bound at 25us).
// Compute per tile: GEMM-form (norm trick), f32x2 FMA, 4p x 4q tiles,
// XOR-8 swizzled transposed targets, norms folded into the mainloop.

#define SP_S 68
#define CM_S 68

// smem layout in floats
#define OFF_PS   0            // pred staging: 2 * 4096
#define OFF_TS   8192         // tgt staging:  2 * 4096
#define OFF_SP   16384        // 64*68 = 4352
#define OFF_STT  20736        // 64*64 = 4096
#define OFF_CM   24832        // 8*68  = 544
#define OFF_RM   25376        // 64
#define OFF_CONF 25440        // 64
#define OFF_CI2  25504        // 64
#define OFF_RED  25568        // 128
#define SMEM_FLOATS 25696     // 102784 bytes

typedef unsigned long long u64;

__device__ __forceinline__ u64 pack2(float x) {
    u64 r; asm("mov.b64 %0, {%1, %1};" : "=l"(r) : "f"(x)); return r;
}
__device__ __forceinline__ void ffma2(u64& d, u64 a, u64 b) {
    asm("fma.rn.f32x2 %0, %1, %2, %0;" : "+l"(d) : "l"(a), "l"(b));
}
__device__ __forceinline__ void unpack2(float& lo, float& hi, u64 v) {
    asm("mov.b64 {%0, %1}, %2;" : "=f"(lo), "=f"(hi) : "l"(v));
}
__device__ __forceinline__ void cp16(unsigned dst, const void* src) {
    asm volatile("cp.async.cg.shared.global [%0], [%1], 16;" :: "r"(dst), "l"(src));
}

__global__ __launch_bounds__(256, 2)
void cross_mse_loss_kernel(const float* __restrict__ inp,
                           const float* __restrict__ tgt,
                           float* __restrict__ out,
                           int nbs, int gridn)
{
    extern __shared__ float sm[];
    float* ps   = sm + OFF_PS;
    float* ts   = sm + OFF_TS;
    float* sp   = sm + OFF_SP;
    float* st_t = sm + OFF_STT;
    float* cm   = sm + OFF_CM;
    float* rm   = sm + OFF_RM;
    float* conf = sm + OFF_CONF;
    float* ci2s = sm + OFF_CI2;
    float* red  = sm + OFF_RED;

    const int tid = threadIdx.x;
    const int lane15 = tid & 15;
    const unsigned smem_base = (unsigned)__cvta_generic_to_shared(sm);

    if (tid < 64) st_t[63 * 64 + tid] = 0.0f;   // d=63 pad row (never rewritten)

    auto issue = [&](int buf, int bs_i) {
        const char* ipb = (const char*)(inp + (size_t)bs_i * 4096);
        const char* tpb = (const char*)(tgt + (size_t)bs_i * 4032);
        unsigned pdst = smem_base + (OFF_PS + buf * 4096) * 4;
        unsigned tdst = smem_base + (OFF_TS + buf * 4096) * 4;
        #pragma unroll
        for (int r = 0; r < 4; r++) {
            int idx = tid + r * 256;
            cp16(pdst + idx * 16, ipb + (size_t)idx * 16);
        }
        #pragma unroll
        for (int r = 0; r < 4; r++) {
            int idx = tid + r * 256;
            if (idx < 1008) cp16(tdst + idx * 16, tpb + (size_t)idx * 16);
        }
        asm volatile("cp.async.commit_group;");
    };

    int bs = blockIdx.x;
    if (bs < nbs) issue(0, bs);

    for (int t = 0; bs < nbs; bs += gridn, t++) {
        const int bs_next = bs + gridn;
        const bool more = bs_next < nbs;
        if (more) {
            issue((t + 1) & 1, bs_next);
            asm volatile("cp.async.wait_group 1;");
        } else {
            asm volatile("cp.async.wait_group 0;");
        }
        __syncthreads();

        const float* psb = ps + (t & 1) * 4096;
        const float* tsb = ts + (t & 1) * 4096;

        // ---- Phase A: staged preds -> sp (+conf), staged tgts -> st_t ----
        #pragma unroll
        for (int r = 0; r < 4; r++) {
            int idx = tid + r * 256;
            int p   = idx >> 4;
            int d4  = (idx & 15) << 2;
            float4 v = *(const float4*)(psb + idx * 4);
            if (d4 == 60) {
                conf[p] = v.w;
                float ci = 1.0f / v.w;
                ci2s[p] = ci * ci;
                v.w = 0.0f;
            }
            *(float4*)(sp + p * SP_S + d4) = v;
        }
        #pragma unroll
        for (int r = 0; r < 4; r++) {
            int idx = tid + r * 256;
            if (idx < 1008) {
                float4 v = *(const float4*)(tsb + idx * 4);
                int e0 = idx << 2;
                float vv[4] = {v.x, v.y, v.z, v.w};
                #pragma unroll
                for (int c = 0; c < 4; c++) {
                    int e = e0 + c;
                    int q = e / 63;
                    int d = e - q * 63;
                    st_t[d * 64 + (((q >> 2) ^ (d & 7)) << 2) + (q & 3)] = vv[c];
                }
            }
        }
        __syncthreads();

        // ---- Mainloop: 4p x 4q, f32x2 along q, norms folded ----
        const int tx = lane15;
        const int ty = tid >> 4;
        const int q0 = tx * 4;
        const int p0 = ty * 4;

        u64 acc[4][2];
        #pragma unroll
        for (int i = 0; i < 4; i++) { acc[i][0] = 0ull; acc[i][1] = 0ull; }
        u64 qa0 = 0ull, qa1 = 0ull;
        u64 pa2[4];
        #pragma unroll
        for (int i = 0; i < 4; i++) pa2[i] = 0ull;

        const float* a0 = sp + p0 * SP_S;

        #pragma unroll
        for (int dc = 0; dc < 64; dc += 4) {
            ulonglong2 b[4];
            #pragma unroll
            for (int d = 0; d < 4; d++) {
                const int dd = dc + d;
                b[d] = *(const ulonglong2*)(st_t + dd * 64 + ((tx ^ (dd & 7)) << 2));
            }
            #pragma unroll
            for (int d = 0; d < 4; d++) {
                ffma2(qa0, b[d].x, b[d].x);
                ffma2(qa1, b[d].y, b[d].y);
            }
            #pragma unroll
            for (int i = 0; i < 4; i++) {
                ulonglong2 a2 = *(const ulonglong2*)(a0 + i * SP_S + dc);
                ffma2(pa2[i], a2.x, a2.x);
                ffma2(pa2[i], a2.y, a2.y);
                float ax0, ax1, ax2, ax3;
                unpack2(ax0, ax1, a2.x);
                unpack2(ax2, ax3, a2.y);
                u64 p0r = pack2(ax0);
                ffma2(acc[i][0], p0r, b[0].x); ffma2(acc[i][1], p0r, b[0].y);
                u64 p1r = pack2(ax1);
                ffma2(acc[i][0], p1r, b[1].x); ffma2(acc[i][1], p1r, b[1].y);
                u64 p2r = pack2(ax2);
                ffma2(acc[i][0], p2r, b[2].x); ffma2(acc[i][1], p2r, b[2].y);
                u64 p3r = pack2(ax3);
                ffma2(acc[i][0], p3r, b[3].x); ffma2(acc[i][1], p3r, b[3].y);
            }
        }

        // ---- Epilogue ----
        float qnr[4];
        unpack2(qnr[0], qnr[1], qa0);
        unpack2(qnr[2], qnr[3], qa1);
        float pnr[4], ci2[4];
        #pragma unroll
        for (int i = 0; i < 4; i++) {
            float lo, hi;
            unpack2(lo, hi, pa2[i]);
            pnr[i] = lo + hi;
            ci2[i] = ci2s[p0 + i];
        }

        float cmin[4] = {1e30f, 1e30f, 1e30f, 1e30f};
        float rmin[4];
        #pragma unroll
        for (int i = 0; i < 4; i++) {
            float dot[4];
            unpack2(dot[0], dot[1], acc[i][0]);
            unpack2(dot[2], dot[3], acc[i][1]);
            float rmn = 1e30f;
            #pragma unroll
            for (int j = 0; j < 4; j++) {
                float d2 = fmaxf(fmaf(-2.0f, dot[j], pnr[i] + qnr[j]), 0.0f);
                rmn = fminf(rmn, d2);
                cmin[j] = fminf(cmin[j], d2 * ci2[i]);
            }
            rmin[i] = rmn;
        }

        #pragma unroll
        for (int m = 1; m < 16; m <<= 1) {
            #pragma unroll
            for (int i = 0; i < 4; i++)
                rmin[i] = fminf(rmin[i], __shfl_xor_sync(0xFFFFFFFFu, rmin[i], m));
        }
        if (lane15 == 0) {
            #pragma unroll
            for (int i = 0; i < 4; i++) rm[p0 + i] = rmin[i];
        }
        #pragma unroll
        for (int j = 0; j < 4; j++)
            cmin[j] = fminf(cmin[j], __shfl_xor_sync(0xFFFFFFFFu, cmin[j], 16));
        if ((tid & 31) < 16) {
            const int w = tid >> 5;
            #pragma unroll
            for (int j = 0; j < 4; j++) cm[w * CM_S + q0 + j] = cmin[j];
        }
        __syncthreads();

        float val = 0.0f;
        if (tid < 64) {
            val = conf[tid] * sqrtf(rm[tid]);
        } else if (tid < 128) {
            int q = tid - 64;
            float m = cm[q];
            #pragma unroll
            for (int u = 1; u < 8; u++) m = fminf(m, cm[u * CM_S + q]);
            val = sqrtf(m);
        }

        if (tid < 128) red[tid] = val;
        __syncthreads();
        if (tid < 64) red[tid] += red[tid + 64];
        __syncthreads();
        if (tid < 32) {
            float s = red[tid] + red[tid + 32];
            #pragma unroll
            for (int off = 16; off > 0; off >>= 1)
                s += __shfl_down_sync(0xFFFFFFFFu, s, off);
            if (tid == 0) out[bs] = s;
        }
    }
}

extern "C" void kernel_launch(void* const* d_in, const int* in_sizes, int n_in,
                              void* d_out, int out_size)
{
    const float* inp = (const float*)d_in[0];
    const float* tgt = (const float*)d_in[1];
    float* out = (float*)d_out;

    const int smem_bytes = SMEM_FLOATS * 4;
    cudaFuncSetAttribute(cross_mse_loss_kernel,
                         cudaFuncAttributeMaxDynamicSharedMemorySize, smem_bytes);

    const int gridn = 304;   // 2 blocks/SM on 152 SMs
    cross_mse_loss_kernel<<<gridn, 256, smem_bytes>>>(inp, tgt, out, 1024, gridn);
}